// round 1
// baseline (speedup 1.0000x reference)
#include <cuda_runtime.h>
#include <math.h>

// Problem constants
#define BB   128
#define SS   1024
#define DIN  1024
#define NQ   8
#define NB   256
#define NH   4
#define TOKN (BB*SS)          // 131072 tokens
#define UOFF ((size_t)TOKN*NB) // offset of uncertainty in d_out

// Scratch (device globals: allocation-free)
__device__ float g_real[TOKN*NQ];   // [l*1024+n][8]  (l=b, n=s)
__device__ float g_imag[TOKN*NQ];
__device__ float g_meas[TOKN*NQ];
__device__ float g_wt[NB*NB];       // unc_w transposed: g_wt[k*256+o] = unc_w[o*256+k]

// ---------- f32x2 packed-FMA helpers ----------
static __device__ __forceinline__ unsigned long long pk2(float lo, float hi) {
    unsigned long long r;
    asm("mov.b64 %0, {%1,%2};" : "=l"(r) : "f"(lo), "f"(hi));
    return r;
}
static __device__ __forceinline__ void upk2(unsigned long long v, float& lo, float& hi) {
    asm("mov.b64 {%0,%1}, %2;" : "=f"(lo), "=f"(hi) : "l"(v));
}
static __device__ __forceinline__ unsigned long long ffma2(unsigned long long a,
                                                           unsigned long long b,
                                                           unsigned long long c) {
    unsigned long long d;
    asm("fma.rn.f32x2 %0, %1, %2, %3;" : "=l"(d) : "l"(a), "l"(b), "l"(c));
    return d;
}

// ---------- transpose unc_w ----------
__global__ void kT(const float* __restrict__ unc_w) {
    int idx = blockIdx.x * blockDim.x + threadIdx.x;
    if (idx < NB*NB) {
        int o = idx >> 8, k = idx & 255;
        g_wt[k*NB + o] = unc_w[idx];
    }
}

// ---------- Stage A: projections + activations + complex parts ----------
// Each thread: 4 consecutive tokens (2 f32x2 pairs), 16 outputs (8 amp + 8 phase).
__global__ void __launch_bounds__(128) kA(const float* __restrict__ x,
                                          const float* __restrict__ aw,
                                          const float* __restrict__ ab,
                                          const float* __restrict__ pw,
                                          const float* __restrict__ pb) {
    __shared__ unsigned long long w2s[16*256];   // 32 KB: (w,w) packed, K-chunk of 256
    const int tid = threadIdx.x;
    const size_t t0 = (size_t)blockIdx.x * 512 + (size_t)tid * 4;

    unsigned long long acc[32];
#pragma unroll
    for (int i = 0; i < 32; i++) acc[i] = 0ull;

    for (int kc = 0; kc < DIN; kc += 256) {
        __syncthreads();
        for (int i = tid; i < 16*256; i += 128) {
            int j = i >> 8, kk = i & 255;
            float w = (j < 8) ? aw[j*DIN + kc + kk] : pw[(j-8)*DIN + kc + kk];
            w2s[i] = pk2(w, w);
        }
        __syncthreads();

        const float4* xr0 = (const float4*)(x + t0*DIN + kc);
        const float4* xr1 = (const float4*)(x + (t0+1)*DIN + kc);
        const float4* xr2 = (const float4*)(x + (t0+2)*DIN + kc);
        const float4* xr3 = (const float4*)(x + (t0+3)*DIN + kc);

        for (int i = 0; i < 64; i++) {
            float4 a0 = __ldg(xr0 + i);
            float4 a1 = __ldg(xr1 + i);
            float4 a2 = __ldg(xr2 + i);
            float4 a3 = __ldg(xr3 + i);
            unsigned long long xA0 = pk2(a0.x, a1.x), xA1 = pk2(a0.y, a1.y);
            unsigned long long xA2 = pk2(a0.z, a1.z), xA3 = pk2(a0.w, a1.w);
            unsigned long long xB0 = pk2(a2.x, a3.x), xB1 = pk2(a2.y, a3.y);
            unsigned long long xB2 = pk2(a2.z, a3.z), xB3 = pk2(a2.w, a3.w);
#pragma unroll
            for (int j = 0; j < 16; j++) {
                const unsigned long long* wp = &w2s[j*256 + 4*i];
                ulonglong2 wa = *(const ulonglong2*)(wp);
                ulonglong2 wb = *(const ulonglong2*)(wp + 2);
                acc[j]    = ffma2(xA0, wa.x, acc[j]);
                acc[j]    = ffma2(xA1, wa.y, acc[j]);
                acc[j]    = ffma2(xA2, wb.x, acc[j]);
                acc[j]    = ffma2(xA3, wb.y, acc[j]);
                acc[16+j] = ffma2(xB0, wa.x, acc[16+j]);
                acc[16+j] = ffma2(xB1, wa.y, acc[16+j]);
                acc[16+j] = ffma2(xB2, wb.x, acc[16+j]);
                acc[16+j] = ffma2(xB3, wb.y, acc[16+j]);
            }
        }
    }

    float ampb[8], phsb[8];
#pragma unroll
    for (int j = 0; j < 8; j++) { ampb[j] = __ldg(ab + j); phsb[j] = __ldg(pb + j); }

#pragma unroll
    for (int grp = 0; grp < 2; grp++) {
        float lo[16], hi[16];
#pragma unroll
        for (int j = 0; j < 16; j++) upk2(acc[grp*16 + j], lo[j], hi[j]);
#pragma unroll
        for (int half = 0; half < 2; half++) {
            const float* v = half ? hi : lo;
            size_t t = t0 + grp*2 + half;
            float orr[8], oii[8];
#pragma unroll
            for (int j = 0; j < 8; j++) {
                float amp = tanhf(v[j] + ampb[j]);
                float ph  = 6.283185307179586f / (1.0f + expf(-(v[8+j] + phsb[j])));
                float s, c;
                sincosf(ph, &s, &c);
                orr[j] = amp * c;
                oii[j] = amp * s;
            }
            float4* pr = (float4*)(g_real + t*NQ);
            float4* pi = (float4*)(g_imag + t*NQ);
            pr[0] = make_float4(orr[0], orr[1], orr[2], orr[3]);
            pr[1] = make_float4(orr[4], orr[5], orr[6], orr[7]);
            pi[0] = make_float4(oii[0], oii[1], oii[2], oii[3]);
            pi[1] = make_float4(oii[4], oii[5], oii[6], oii[7]);
        }
    }
}

// ---------- Stage B: dual MHA (real & imag) + out_proj + |.| ----------
// Block = one n (s index), thread = one l (b index). L = 128.
__global__ void __launch_bounds__(128) kB(const float* __restrict__ ipw,
                                          const float* __restrict__ ipb,
                                          const float* __restrict__ opw,
                                          const float* __restrict__ opb) {
    __shared__ float ks[2][128][8];
    __shared__ float vs[2][128][8];
    __shared__ float s_ipw[24][8];
    __shared__ float s_ipb[24];
    __shared__ float s_opw[8][8];
    __shared__ float s_opb[8];

    const int l = threadIdx.x;
    const int n = blockIdx.x;

    if (l < 24) {
        s_ipb[l] = ipb[l];
#pragma unroll
        for (int e = 0; e < 8; e++) s_ipw[l][e] = ipw[l*8 + e];
    }
    if (l < 8) {
        s_opb[l] = opb[l];
#pragma unroll
        for (int j = 0; j < 8; j++) s_opw[l][j] = opw[l*8 + j];
    }

    const size_t base = ((size_t)l * SS + n) * NQ;
    float st[2][8];
    {
        float4 r0 = *(const float4*)(g_real + base);
        float4 r1 = *(const float4*)(g_real + base + 4);
        float4 i0 = *(const float4*)(g_imag + base);
        float4 i1 = *(const float4*)(g_imag + base + 4);
        st[0][0]=r0.x; st[0][1]=r0.y; st[0][2]=r0.z; st[0][3]=r0.w;
        st[0][4]=r1.x; st[0][5]=r1.y; st[0][6]=r1.z; st[0][7]=r1.w;
        st[1][0]=i0.x; st[1][1]=i0.y; st[1][2]=i0.z; st[1][3]=i0.w;
        st[1][4]=i1.x; st[1][5]=i1.y; st[1][6]=i1.z; st[1][7]=i1.w;
    }
    __syncthreads();  // weights ready

    float qb[2][8];
#pragma unroll
    for (int p = 0; p < 2; p++) {
#pragma unroll
        for (int j = 0; j < 8; j++) {
            float q = s_ipb[j], k = s_ipb[8+j], v = s_ipb[16+j];
#pragma unroll
            for (int e = 0; e < 8; e++) {
                q = fmaf(s_ipw[j][e],    st[p][e], q);
                k = fmaf(s_ipw[8+j][e],  st[p][e], k);
                v = fmaf(s_ipw[16+j][e], st[p][e], v);
            }
            qb[p][j] = q;
            ks[p][l][j] = k;
            vs[p][l][j] = v;
        }
    }
    __syncthreads();

    // Single-pass softmax (scores bounded ~11.3 — no overflow risk)
    float ent[2][8];
#pragma unroll
    for (int p = 0; p < 2; p++) {
#pragma unroll
        for (int h = 0; h < NH; h++) {
            float q0 = qb[p][2*h], q1 = qb[p][2*h+1];
            float den = 0.f, o0 = 0.f, o1 = 0.f;
            for (int m = 0; m < 128; m++) {
                float2 kk = *(const float2*)&ks[p][m][2*h];
                float sc = fmaf(q0, kk.x, q1*kk.y) * 0.70710678118654752f;
                float e  = __expf(sc);
                float2 vv = *(const float2*)&vs[p][m][2*h];
                den += e;
                o0 = fmaf(e, vv.x, o0);
                o1 = fmaf(e, vv.y, o1);
            }
            float inv = __fdividef(1.0f, den);
            ent[p][2*h]   = o0 * inv;
            ent[p][2*h+1] = o1 * inv;
        }
    }

    float out[8];
#pragma unroll
    for (int e = 0; e < 8; e++) {
        float er = s_opb[e], ei = s_opb[e];
#pragma unroll
        for (int j = 0; j < 8; j++) {
            er = fmaf(s_opw[e][j], ent[0][j], er);
            ei = fmaf(s_opw[e][j], ent[1][j], ei);
        }
        out[e] = sqrtf(er*er + ei*ei);
    }
    float4* pm = (float4*)(g_meas + base);
    pm[0] = make_float4(out[0], out[1], out[2], out[3]);
    pm[1] = make_float4(out[4], out[5], out[6], out[7]);
}

// ---------- Stage C: meas->compressed (written) -> sigmoid(unc GEMM) ----------
// Block = 64 tokens x 256 outputs. Phase 1: thread-per-output-k computes
// compressed, writes to d_out + smem (padded [k][66]). Phase 2: f32x2 GEMM,
// thread = 8 tokens (4 pairs) x 8 outputs, K=256, weights from transposed g_wt.
__global__ void __launch_bounds__(256) kC(const float* __restrict__ meas_w,
                                          const float* __restrict__ meas_b,
                                          const float* __restrict__ unc_b,
                                          float* __restrict__ out) {
    extern __shared__ float sm[];
    float* comp_s = sm;               // 256 * 66 floats
    float* meas_s = sm + 256*66;      // 64 * 8 floats

    const size_t T0 = (size_t)blockIdx.x * 64;
    const int tid = threadIdx.x;

    if (tid < 128)
        ((float4*)meas_s)[tid] = __ldg((const float4*)(g_meas + T0*NQ) + tid);
    __syncthreads();

    // Phase 1
    {
        const int k = tid;
        float4 w0 = __ldg((const float4*)(meas_w + k*NQ));
        float4 w1 = __ldg((const float4*)(meas_w + k*NQ) + 1);
        float bb = __ldg(meas_b + k);
        float* orow = out + T0*NB + k;
#pragma unroll 4
        for (int t = 0; t < 64; t++) {
            const float* mm = meas_s + t*NQ;
            float c = bb;
            c = fmaf(w0.x, mm[0], c); c = fmaf(w0.y, mm[1], c);
            c = fmaf(w0.z, mm[2], c); c = fmaf(w0.w, mm[3], c);
            c = fmaf(w1.x, mm[4], c); c = fmaf(w1.y, mm[5], c);
            c = fmaf(w1.z, mm[6], c); c = fmaf(w1.w, mm[7], c);
            comp_s[k*66 + t] = c;
            orow[(size_t)t*NB] = c;
        }
    }
    __syncthreads();

    // Phase 2
    const int lane = tid & 31, warp = tid >> 5;
    const int o0 = lane * 8;
    const int t0 = warp * 8;

    unsigned long long acc[4][8];
#pragma unroll
    for (int p = 0; p < 4; p++)
#pragma unroll
        for (int j = 0; j < 8; j++) acc[p][j] = 0ull;

#pragma unroll 2
    for (int k = 0; k < NB; k++) {
        unsigned long long xp0 = *(const unsigned long long*)&comp_s[k*66 + t0];
        unsigned long long xp1 = *(const unsigned long long*)&comp_s[k*66 + t0 + 2];
        unsigned long long xp2 = *(const unsigned long long*)&comp_s[k*66 + t0 + 4];
        unsigned long long xp3 = *(const unsigned long long*)&comp_s[k*66 + t0 + 6];
        float4 wa = __ldg((const float4*)(g_wt + k*NB + o0));
        float4 wb = __ldg((const float4*)(g_wt + k*NB + o0 + 4));
        unsigned long long w2[8];
        w2[0] = pk2(wa.x, wa.x); w2[1] = pk2(wa.y, wa.y);
        w2[2] = pk2(wa.z, wa.z); w2[3] = pk2(wa.w, wa.w);
        w2[4] = pk2(wb.x, wb.x); w2[5] = pk2(wb.y, wb.y);
        w2[6] = pk2(wb.z, wb.z); w2[7] = pk2(wb.w, wb.w);
#pragma unroll
        for (int j = 0; j < 8; j++) {
            acc[0][j] = ffma2(xp0, w2[j], acc[0][j]);
            acc[1][j] = ffma2(xp1, w2[j], acc[1][j]);
            acc[2][j] = ffma2(xp2, w2[j], acc[2][j]);
            acc[3][j] = ffma2(xp3, w2[j], acc[3][j]);
        }
    }

    float ub[8];
#pragma unroll
    for (int j = 0; j < 8; j++) ub[j] = __ldg(unc_b + o0 + j);

    float* uout = out + UOFF;
#pragma unroll
    for (int p = 0; p < 4; p++) {
        size_t ta = T0 + t0 + 2*p;
        float va[8], vb[8];
#pragma unroll
        for (int j = 0; j < 8; j++) upk2(acc[p][j], va[j], vb[j]);
#pragma unroll
        for (int j = 0; j < 8; j++) {
            va[j] = 1.0f / (1.0f + __expf(-(va[j] + ub[j])));
            vb[j] = 1.0f / (1.0f + __expf(-(vb[j] + ub[j])));
        }
        float4* pa = (float4*)(uout + ta*NB + o0);
        pa[0] = make_float4(va[0], va[1], va[2], va[3]);
        pa[1] = make_float4(va[4], va[5], va[6], va[7]);
        float4* pbp = (float4*)(uout + (ta+1)*NB + o0);
        pbp[0] = make_float4(vb[0], vb[1], vb[2], vb[3]);
        pbp[1] = make_float4(vb[4], vb[5], vb[6], vb[7]);
    }
}

extern "C" void kernel_launch(void* const* d_in, const int* in_sizes, int n_in,
                              void* d_out, int out_size) {
    const float* x         = (const float*)d_in[0];
    const float* amp_w     = (const float*)d_in[1];
    const float* amp_b     = (const float*)d_in[2];
    const float* phase_w   = (const float*)d_in[3];
    const float* phase_b   = (const float*)d_in[4];
    const float* in_proj_w = (const float*)d_in[5];
    const float* in_proj_b = (const float*)d_in[6];
    const float* out_proj_w= (const float*)d_in[7];
    const float* out_proj_b= (const float*)d_in[8];
    const float* meas_w    = (const float*)d_in[9];
    const float* meas_b    = (const float*)d_in[10];
    const float* unc_w     = (const float*)d_in[11];
    const float* unc_b     = (const float*)d_in[12];
    float* out = (float*)d_out;

    const int kc_smem = 256*66*4 + 64*8*4;  // 69632 bytes
    cudaFuncSetAttribute(kC, cudaFuncAttributeMaxDynamicSharedMemorySize, kc_smem);

    kT<<<64, 1024>>>(unc_w);
    kA<<<256, 128>>>(x, amp_w, amp_b, phase_w, phase_b);
    kB<<<1024, 128>>>(in_proj_w, in_proj_b, out_proj_w, out_proj_b);
    kC<<<2048, 256, kc_smem>>>(meas_w, meas_b, unc_b, out);
}